// round 13
// baseline (speedup 1.0000x reference)
#include <cuda_runtime.h>
#include <stdint.h>

#define MAXB 262144
#define TSPB 64             // trunk samples per block (3 CTAs/SM)
#define ESPB 512            // expert samples per block (2 per thread)
#define NE 30
#define H0S 68              // h0T row stride (floats): 64 + 4 pad
#define NDESC_MAX (MAXB / ESPB + NE + 2)

typedef unsigned long long u64;

// ---------------- device scratch (allocation-free) ----------------
__device__ float g_h[MAXB * 64];
__device__ int   g_eid[MAXB];
__device__ int   g_perm[MAXB];
__device__ int   g_cnt[32];          // statically zero for the first call
__device__ int   g_cursor[32];
__device__ int   g_desc_e[NDESC_MAX];
__device__ int   g_desc_s[NDESC_MAX];
__device__ int   g_desc_c[NDESC_MAX];
__device__ int   g_ndesc;

// ---------------- packed f32x2 helpers ----------------
__device__ __forceinline__ u64 pk2(float lo, float hi) {
    u64 r; asm("mov.b64 %0,{%1,%2};" : "=l"(r) : "f"(lo), "f"(hi)); return r;
}
__device__ __forceinline__ void upk2(u64 v, float& lo, float& hi) {
    asm("mov.b64 {%0,%1},%2;" : "=f"(lo), "=f"(hi) : "l"(v));
}
__device__ __forceinline__ u64 fma2v(u64 a, u64 b, u64 c) {
    u64 d; asm("fma.rn.f32x2 %0,%1,%2,%3;" : "=l"(d) : "l"(a), "l"(b), "l"(c)); return d;
}
__device__ __forceinline__ void fma2acc(u64& d, u64 a, u64 b) {
    asm("fma.rn.f32x2 %0,%1,%2,%0;" : "+l"(d) : "l"(a), "l"(b));
}
__device__ __forceinline__ u64 mul2v(u64 a, u64 b) {
    u64 d; asm("mul.rn.f32x2 %0,%1,%2;" : "=l"(d) : "l"(a), "l"(b)); return d;
}

// packed pair tanh, Pade[7/6], FMA-pipe only (no MUFU)
__device__ __forceinline__ float2 tanh2(float a, float b) {
    a = fminf(fmaxf(a, -5.0f), 5.0f);
    b = fminf(fmaxf(b, -5.0f), 5.0f);
    u64 cc = pk2(a, b);
    u64 uu = mul2v(cc, cc);
    u64 p = fma2v(uu, pk2(7.3996004e-6f, 7.3996004e-6f), pk2(2.7972028e-3f, 2.7972028e-3f));
    p = fma2v(uu, p, pk2(0.12820513f, 0.12820513f));
    p = fma2v(uu, p, pk2(1.0f, 1.0f));
    p = mul2v(p, cc);
    u64 q = fma2v(uu, pk2(2.0718881e-4f, 2.0718881e-4f), pk2(0.023310023f, 0.023310023f));
    q = fma2v(uu, q, pk2(0.46153846f, 0.46153846f));
    q = fma2v(uu, q, pk2(1.0f, 1.0f));
    float q0, q1; upk2(q, q0, q1);
    float r0 = __int_as_float(0x7EF311C3 - __float_as_int(q0));
    float r1 = __int_as_float(0x7EF311C3 - __float_as_int(q1));
    u64 rr = pk2(r0, r1);
    u64 nq = mul2v(q, pk2(-1.0f, -1.0f));
    u64 two = pk2(2.0f, 2.0f);
    rr = mul2v(rr, fma2v(nq, rr, two));
    rr = mul2v(rr, fma2v(nq, rr, two));
    u64 res = mul2v(p, rr);
    float o0, o1; upk2(res, o0, o1);
    return make_float2(o0, o1);
}

// ================= K1: trunk — TSPB=64, 3 CTAs/SM =================
#define T_OFF_W0  0
#define T_OFF_B0  384
#define T_OFF_B1  512
#define T_OFF_W1  576
#define T_OFF_H0T 8768
#define T_OFF_INT (8768 + 128 * H0S)          // 17472
#define T_SMEM_FLOATS (T_OFF_INT + 32)
#define T_SMEM_BYTES  (T_SMEM_FLOATS * 4)     // 70016 B -> 3 CTAs/SM

extern __shared__ float smem[];

__global__ __launch_bounds__(256, 3)
void trunk_kernel(const float* __restrict__ x,
                  const int* __restrict__ nn,
                  const int* __restrict__ ll,
                  const int* __restrict__ mm,
                  const float* __restrict__ W0, const float* __restrict__ b0,
                  const float* __restrict__ W1, const float* __restrict__ b1,
                  int B)
{
    float* sW0  = smem + T_OFF_W0;
    float* sb0  = smem + T_OFF_B0;
    float* sb1  = smem + T_OFF_B1;
    float* sW1  = smem + T_OFF_W1;
    float* sH0T = smem + T_OFF_H0T;
    int*   sCnt = (int*)(smem + T_OFF_INT);

    const int t = threadIdx.x;
    const int base = blockIdx.x * TSPB;

    for (int i = t; i < 384; i += 256) sW0[i] = W0[i];   // FIX: full 384 staged
    if (t < 128) sb0[t] = b0[t];
    #pragma unroll
    for (int i = 0; i < 8; i++) ((float4*)sW1)[t + 256 * i] = ((const float4*)W1)[t + 256 * i];
    if (t < 64) sb1[t] = b1[t];
    if (t < 31) sCnt[t] = 0;
    __syncthreads();

    // ---- pass A: h0 = tanh(x@W0+b0) -> h0T[j][s], 4 threads/sample ----
    const int sa = t & 63;
    const int ug = (t >> 6) * 32;        // unit base: 0,32,64,96
    const int s = base + sa;
    const bool active = (s < B);
    float x0 = 0.f, x1 = 0.f, x2 = 0.f;
    if (active) {
        x0 = x[3 * s + 0];
        x1 = x[3 * s + 1];
        x2 = x[3 * s + 2];
    }
    if (t < 64) {
        int eid = NE;
        if (active) {
            int n = nn[s], l = ll[s], m = mm[s];
            eid = ((n - 1) * n * (2 * n - 1)) / 6 + l * l + l + m;
            g_eid[s] = eid;
        }
        if (eid < NE) atomicAdd(&sCnt[eid], 1);
    }
    {
        const u64 xx0 = pk2(x0, x0);
        const u64 xx1 = pk2(x1, x1);
        const u64 xx2 = pk2(x2, x2);
        float* hdst = sH0T + ug * H0S + sa;
        #pragma unroll 4
        for (int up = 0; up < 16; up++) {
            const int u = ug + 2 * up;
            float2 wa2 = *(const float2*)(sW0 + u);
            float2 wb2 = *(const float2*)(sW0 + 128 + u);
            float2 wc2 = *(const float2*)(sW0 + 256 + u);
            float2 bp2 = *(const float2*)(sb0 + u);
            u64 pre = fma2v(xx0, pk2(wa2.x, wa2.y),
                      fma2v(xx1, pk2(wb2.x, wb2.y),
                      fma2v(xx2, pk2(wc2.x, wc2.y), pk2(bp2.x, bp2.y))));
            float p0, p1; upk2(pre, p0, p1);
            float2 h = tanh2(p0, p1);
            hdst[0]   = h.x;
            hdst[H0S] = h.y;
            hdst += 2 * H0S;
        }
    }
    __syncthreads();

    if (t < 30) {
        int c = sCnt[t];
        if (c) atomicAdd(&g_cnt[t], c);
    }

    // ---- pass B: C[64x64] = h0T @ W1 ; og=t&7 (8 outs), sg=t>>3 (2 samples) ----
    const int og = t & 7;
    const int sg = t >> 3;               // 0..31 -> samples 2sg, 2sg+1
    u64 acc[8];
    {
        const ulonglong2* bi = (const ulonglong2*)(sb1 + og * 8);
        ulonglong2 b01 = bi[0], b23 = bi[1];
        acc[0] = b01.x; acc[1] = b01.y; acc[2] = b23.x; acc[3] = b23.y;
        acc[4] = b01.x; acc[5] = b01.y; acc[6] = b23.x; acc[7] = b23.y;
    }
    {
        const float* hrow = sH0T + 2 * sg;
        const float* wrow = sW1 + og * 8;
        #pragma unroll 8
        for (int j = 0; j < 128; j++) {
            u64 hp = *(const u64*)(hrow + j * H0S);
            float h0, h1; upk2(hp, h0, h1);
            u64 hh0 = pk2(h0, h0);
            u64 hh1 = pk2(h1, h1);
            ulonglong2 wv0 = *(const ulonglong2*)(wrow + j * 64);
            ulonglong2 wv1 = *(const ulonglong2*)(wrow + j * 64 + 4);
            fma2acc(acc[0], hh0, wv0.x); fma2acc(acc[1], hh0, wv0.y);
            fma2acc(acc[2], hh0, wv1.x); fma2acc(acc[3], hh0, wv1.y);
            fma2acc(acc[4], hh1, wv0.x); fma2acc(acc[5], hh1, wv0.y);
            fma2acc(acc[6], hh1, wv1.x); fma2acc(acc[7], hh1, wv1.y);
        }
    }
    // epilogue: tanh -> g_h[s][64] (coalesced across og)
    #pragma unroll
    for (int s2 = 0; s2 < 2; s2++) {
        const int gs = base + 2 * sg + s2;
        if (gs < B) {
            float a, b, c, d;
            upk2(acc[4 * s2 + 0], a, b);
            upk2(acc[4 * s2 + 1], c, d);
            float2 t01 = tanh2(a, b);
            float2 t23 = tanh2(c, d);
            float* hr = g_h + gs * 64 + og * 8;
            ((float4*)hr)[0] = make_float4(t01.x, t01.y, t23.x, t23.y);
            upk2(acc[4 * s2 + 2], a, b);
            upk2(acc[4 * s2 + 3], c, d);
            t01 = tanh2(a, b);
            t23 = tanh2(c, d);
            ((float4*)hr)[1] = make_float4(t01.x, t01.y, t23.x, t23.y);
        }
    }
}

// ================= K2: scan + descriptors =================
__global__ void scan_kernel() {
    __shared__ int sStart[NE], sNb[NE], sDb[NE];
    const int t = threadIdx.x;
    if (t == 0) {
        int run = 0, nd = 0;
        for (int e = 0; e < NE; e++) {
            sStart[e] = run;
            int c = g_cnt[e];
            int nb = (c + ESPB - 1) / ESPB;
            sNb[e] = nb;
            sDb[e] = nd;
            nd += nb;
            run += c;
        }
        g_ndesc = nd;
    }
    __syncthreads();
    if (t < NE) {
        g_cursor[t] = sStart[t];
        const int nb = sNb[t], db = sDb[t], st = sStart[t], c = g_cnt[t];
        for (int b = 0; b < nb; b++) {
            g_desc_e[db + b] = t;
            g_desc_s[db + b] = st + b * ESPB;
            int rem = c - b * ESPB;
            g_desc_c[db + b] = rem < ESPB ? rem : ESPB;
        }
    }
}

// ================= K3: scatter into sorted perm =================
__global__ __launch_bounds__(256)
void scatter_kernel(int B) {
    __shared__ int sCnt[32], sRes[32];
    const int t = threadIdx.x;
    const int s = blockIdx.x * 256 + t;
    if (t < 32) sCnt[t] = 0;
    __syncthreads();
    int eid = 31;
    int myloc = 0;
    if (s < B) {
        eid = g_eid[s];
        myloc = atomicAdd(&sCnt[eid], 1);
    }
    __syncthreads();
    if (t < NE) {
        int c = sCnt[t];
        sRes[t] = c ? atomicAdd(&g_cursor[t], c) : 0;
    }
    __syncthreads();
    if (s < B && eid < NE) g_perm[sRes[eid] + myloc] = s;
}

// ================= K4: expert heads — 2 samples/thread (unchanged R11) =================
__global__ __launch_bounds__(256)
void expert_kernel(const float* __restrict__ Wa, const float* __restrict__ ba,
                   const float* __restrict__ Wb, const float* __restrict__ bb,
                   float* __restrict__ out)
{
    __shared__ float sWa[2048];
    __shared__ float sba[32], sWb0[32], sWb1[32], sbb[2];

    const int bid = blockIdx.x;
    if (bid >= g_ndesc) return;
    const int t = threadIdx.x;
    const int e   = g_desc_e[bid];
    const int st  = g_desc_s[bid];
    const int cnt = g_desc_c[bid];

    const bool v0 = (t < cnt);
    const bool v1 = (t + 256 < cnt);
    const int s0 = g_perm[st + (v0 ? t : 0)];
    const int s1 = g_perm[st + (v1 ? t + 256 : 0)];
    const float4* ha = (const float4*)(g_h + s0 * 64);
    const float4* hb = (const float4*)(g_h + s1 * 64);

    float4 hca = ha[0], hna = ha[1];
    float4 hcb = hb[0], hnb = hb[1];

    ((float4*)sWa)[t]       = ((const float4*)(Wa + e * 2048))[t];
    ((float4*)sWa)[t + 256] = ((const float4*)(Wa + e * 2048))[t + 256];
    if (t < 32) {
        sba[t]  = ba[e * 32 + t];
        sWb0[t] = Wb[e * 64 + 2 * t];
        sWb1[t] = Wb[e * 64 + 2 * t + 1];
    }
    if (t < 2) sbb[t] = bb[e * 2 + t];
    __syncthreads();

    u64 ga[16], gb[16];
    #pragma unroll
    for (int q = 0; q < 16; q++) {
        u64 b2 = *(const u64*)(sba + 2 * q);
        ga[q] = b2; gb[q] = b2;
    }

    #pragma unroll
    for (int q = 0; q < 16; q++) {
        float4 h4a = hca, h4b = hcb;
        hca = hna; hcb = hnb;
        if (q < 14) { hna = ha[q + 2]; hnb = hb[q + 2]; }
        const int j0 = 4 * q;
        #pragma unroll
        for (int c4 = 0; c4 < 4; c4++) {
            const float fa = (c4 == 0) ? h4a.x : (c4 == 1) ? h4a.y : (c4 == 2) ? h4a.z : h4a.w;
            const float fb = (c4 == 0) ? h4b.x : (c4 == 1) ? h4b.y : (c4 == 2) ? h4b.z : h4b.w;
            const u64 hha = pk2(fa, fa);
            const u64 hhb = pk2(fb, fb);
            const ulonglong2* w = (const ulonglong2*)(sWa + (j0 + c4) * 32);
            #pragma unroll
            for (int r = 0; r < 8; r++) {
                ulonglong2 wv = w[r];
                fma2acc(ga[2*r],   hha, wv.x);
                fma2acc(gb[2*r],   hhb, wv.x);
                fma2acc(ga[2*r+1], hha, wv.y);
                fma2acc(gb[2*r+1], hhb, wv.y);
            }
        }
    }

    u64 Pa0 = 0, Pa1 = 0, Pb0 = 0, Pb1 = 0;
    #pragma unroll
    for (int q = 0; q < 16; q++) {
        const u64 w0 = *(const u64*)(sWb0 + 2 * q);
        const u64 w1 = *(const u64*)(sWb1 + 2 * q);
        float a, b;
        upk2(ga[q], a, b);
        float2 tg = tanh2(a, b);
        u64 G = pk2(tg.x, tg.y);
        fma2acc(Pa0, G, w0);
        fma2acc(Pa1, G, w1);
        upk2(gb[q], a, b);
        tg = tanh2(a, b);
        G = pk2(tg.x, tg.y);
        fma2acc(Pb0, G, w0);
        fma2acc(Pb1, G, w1);
    }
    {
        float u, v;
        upk2(Pa0, u, v); float p0 = u + v + sbb[0];
        upk2(Pa1, u, v); float p1 = u + v + sbb[1];
        float r = rsqrtf(fmaf(p0, p0, fmaf(p1, p1, 1e-6f)));
        if (v0) ((float2*)out)[s0] = make_float2(p0 * r, p1 * r);
        upk2(Pb0, u, v); p0 = u + v + sbb[0];
        upk2(Pb1, u, v); p1 = u + v + sbb[1];
        r = rsqrtf(fmaf(p0, p0, fmaf(p1, p1, 1e-6f)));
        if (v1) ((float2*)out)[s1] = make_float2(p0 * r, p1 * r);
    }
}

// ================= K5: reset histogram for next call (runs last) =================
__global__ void init_kernel() {
    if (threadIdx.x < 32) g_cnt[threadIdx.x] = 0;
}

// ================= host =================
extern "C" void kernel_launch(void* const* d_in, const int* in_sizes, int n_in,
                              void* d_out, int out_size) {
    const float* x  = (const float*)d_in[0];
    const int*   nn = (const int*)  d_in[1];
    const int*   ll = (const int*)  d_in[2];
    const int*   mm = (const int*)  d_in[3];
    const float* W0 = (const float*)d_in[4];
    const float* b0 = (const float*)d_in[5];
    const float* W1 = (const float*)d_in[6];
    const float* b1 = (const float*)d_in[7];
    const float* Wa = (const float*)d_in[8];
    const float* ba = (const float*)d_in[9];
    const float* Wb = (const float*)d_in[10];
    const float* bb = (const float*)d_in[11];
    float* out = (float*)d_out;

    const int B = in_sizes[1];

    static int attr_set = 0;
    if (!attr_set) {
        cudaFuncSetAttribute(trunk_kernel,
                             cudaFuncAttributeMaxDynamicSharedMemorySize, T_SMEM_BYTES);
        attr_set = 1;
    }

    trunk_kernel<<<(B + TSPB - 1) / TSPB, 256, T_SMEM_BYTES>>>(
        x, nn, ll, mm, W0, b0, W1, b1, B);
    scan_kernel<<<1, 32>>>();
    scatter_kernel<<<(B + 255) / 256, 256>>>(B);
    expert_kernel<<<(B + ESPB - 1) / ESPB + NE, 256>>>(Wa, ba, Wb, bb, out);
    init_kernel<<<1, 32>>>();
}

// round 16
// speedup vs baseline: 1.5422x; 1.5422x over previous
#include <cuda_runtime.h>
#include <cuda_fp16.h>
#include <stdint.h>

#define MAXB 262144
#define TSPB 128            // trunk samples per block (R11 config)
#define ESPB 512            // expert samples per block (2 per thread)
#define NE 30
#define H0S 132             // h0T row stride (floats)
#define NDESC_MAX (MAXB / ESPB + NE + 2)

typedef unsigned long long u64;

// ---------------- device scratch (allocation-free) ----------------
__device__ __half g_h[MAXB * 64];    // h in fp16 (|h|<1): halves DRAM/L2 traffic
__device__ int   g_eid[MAXB];
__device__ int   g_perm[MAXB];
__device__ int   g_cnt[32];          // statically zero for the first call
__device__ int   g_cursor[32];
__device__ int   g_desc_e[NDESC_MAX];
__device__ int   g_desc_s[NDESC_MAX];
__device__ int   g_desc_c[NDESC_MAX];
__device__ int   g_ndesc;

// ---------------- packed f32x2 helpers ----------------
__device__ __forceinline__ u64 pk2(float lo, float hi) {
    u64 r; asm("mov.b64 %0,{%1,%2};" : "=l"(r) : "f"(lo), "f"(hi)); return r;
}
__device__ __forceinline__ void upk2(u64 v, float& lo, float& hi) {
    asm("mov.b64 {%0,%1},%2;" : "=f"(lo), "=f"(hi) : "l"(v));
}
__device__ __forceinline__ u64 fma2v(u64 a, u64 b, u64 c) {
    u64 d; asm("fma.rn.f32x2 %0,%1,%2,%3;" : "=l"(d) : "l"(a), "l"(b), "l"(c)); return d;
}
__device__ __forceinline__ void fma2acc(u64& d, u64 a, u64 b) {
    asm("fma.rn.f32x2 %0,%1,%2,%0;" : "+l"(d) : "l"(a), "l"(b));
}
__device__ __forceinline__ u64 mul2v(u64 a, u64 b) {
    u64 d; asm("mul.rn.f32x2 %0,%1,%2;" : "=l"(d) : "l"(a), "l"(b)); return d;
}
__device__ __forceinline__ uint32_t f2h2(float a, float b) {
    __half2 h = __floats2half2_rn(a, b);
    return *(uint32_t*)&h;
}
__device__ __forceinline__ float2 h22f2(uint32_t v) {
    return __half22float2(*(__half2*)&v);
}

// packed pair tanh, Pade[7/6], FMA-pipe only (no MUFU)
__device__ __forceinline__ float2 tanh2(float a, float b) {
    a = fminf(fmaxf(a, -5.0f), 5.0f);
    b = fminf(fmaxf(b, -5.0f), 5.0f);
    u64 cc = pk2(a, b);
    u64 uu = mul2v(cc, cc);
    u64 p = fma2v(uu, pk2(7.3996004e-6f, 7.3996004e-6f), pk2(2.7972028e-3f, 2.7972028e-3f));
    p = fma2v(uu, p, pk2(0.12820513f, 0.12820513f));
    p = fma2v(uu, p, pk2(1.0f, 1.0f));
    p = mul2v(p, cc);
    u64 q = fma2v(uu, pk2(2.0718881e-4f, 2.0718881e-4f), pk2(0.023310023f, 0.023310023f));
    q = fma2v(uu, q, pk2(0.46153846f, 0.46153846f));
    q = fma2v(uu, q, pk2(1.0f, 1.0f));
    float q0, q1; upk2(q, q0, q1);
    float r0 = __int_as_float(0x7EF311C3 - __float_as_int(q0));
    float r1 = __int_as_float(0x7EF311C3 - __float_as_int(q1));
    u64 rr = pk2(r0, r1);
    u64 nq = mul2v(q, pk2(-1.0f, -1.0f));
    u64 two = pk2(2.0f, 2.0f);
    rr = mul2v(rr, fma2v(nq, rr, two));
    rr = mul2v(rr, fma2v(nq, rr, two));
    u64 res = mul2v(p, rr);
    float o0, o1; upk2(res, o0, o1);
    return make_float2(o0, o1);
}

// ================= K1: trunk (R11 config: 256 thr, 2 CTAs/SM) =========
#define T_OFF_W0  0
#define T_OFF_B0  384
#define T_OFF_B1  512
#define T_OFF_W1  576
#define T_OFF_H0T 8768
#define T_OFF_INT (8768 + 128 * H0S)
#define T_SMEM_FLOATS (T_OFF_INT + 32)
#define T_SMEM_BYTES  (T_SMEM_FLOATS * 4)    // ~102.8 KB -> 2 CTAs/SM

extern __shared__ float smem[];

__global__ __launch_bounds__(256, 2)
void trunk_kernel(const float* __restrict__ x,
                  const int* __restrict__ nn,
                  const int* __restrict__ ll,
                  const int* __restrict__ mm,
                  const float* __restrict__ W0, const float* __restrict__ b0,
                  const float* __restrict__ W1, const float* __restrict__ b1,
                  int B)
{
    float* sW0  = smem + T_OFF_W0;
    float* sb0  = smem + T_OFF_B0;
    float* sb1  = smem + T_OFF_B1;
    float* sW1  = smem + T_OFF_W1;
    float* sH0T = smem + T_OFF_H0T;
    int*   sCnt = (int*)(smem + T_OFF_INT);

    const int t = threadIdx.x;
    const int base = blockIdx.x * TSPB;

    for (int i = t; i < 384; i += 256) sW0[i] = W0[i];
    if (t < 128) sb0[t] = b0[t];
    #pragma unroll
    for (int i = 0; i < 8; i++) ((float4*)sW1)[t + 256 * i] = ((const float4*)W1)[t + 256 * i];
    if (t < 64) sb1[t] = b1[t];
    if (t < 31) sCnt[t] = 0;
    __syncthreads();

    // ---- pass A: h0 = tanh(x@W0+b0) -> h0T[j][s], 2 threads/sample ----
    const int sa = t & 127;
    const int ubase = (t >> 7) * 64;
    const int s = base + sa;
    const bool active = (s < B);
    float x0 = 0.f, x1 = 0.f, x2 = 0.f;
    if (active) {
        x0 = x[3 * s + 0];
        x1 = x[3 * s + 1];
        x2 = x[3 * s + 2];
    }
    if (t < 128) {
        int eid = NE;
        if (active) {
            int n = nn[s], l = ll[s], m = mm[s];
            eid = ((n - 1) * n * (2 * n - 1)) / 6 + l * l + l + m;
            g_eid[s] = eid;
        }
        if (eid < NE) atomicAdd(&sCnt[eid], 1);
    }
    {
        const u64 xx0 = pk2(x0, x0);
        const u64 xx1 = pk2(x1, x1);
        const u64 xx2 = pk2(x2, x2);
        float* hdst = sH0T + ubase * H0S + sa;
        #pragma unroll 8
        for (int up = 0; up < 32; up++) {
            const int u = ubase + 2 * up;
            float2 wa2 = *(const float2*)(sW0 + u);
            float2 wb2 = *(const float2*)(sW0 + 128 + u);
            float2 wc2 = *(const float2*)(sW0 + 256 + u);
            float2 bp2 = *(const float2*)(sb0 + u);
            u64 pre = fma2v(xx0, pk2(wa2.x, wa2.y),
                      fma2v(xx1, pk2(wb2.x, wb2.y),
                      fma2v(xx2, pk2(wc2.x, wc2.y), pk2(bp2.x, bp2.y))));
            float p0, p1; upk2(pre, p0, p1);
            float2 h = tanh2(p0, p1);
            hdst[0]   = h.x;
            hdst[H0S] = h.y;
            hdst += 2 * H0S;
        }
    }
    __syncthreads();

    if (t < 30) {
        int c = sCnt[t];
        if (c) atomicAdd(&g_cnt[t], c);
    }

    // ---- pass B: C[128x64] = h0T @ W1 ; og=t&7 (8 outs), sg=t>>3 (4 samples) ----
    const int og = t & 7;
    const int sg = t >> 3;
    u64 acc[16];
    {
        const ulonglong2* bi = (const ulonglong2*)(sb1 + og * 8);
        ulonglong2 b01 = bi[0], b23 = bi[1];
        #pragma unroll
        for (int s4 = 0; s4 < 4; s4++) {
            acc[s4 * 4 + 0] = b01.x; acc[s4 * 4 + 1] = b01.y;
            acc[s4 * 4 + 2] = b23.x; acc[s4 * 4 + 3] = b23.y;
        }
    }
    {
        const float* hrow = sH0T + 4 * sg;
        const float* wrow = sW1 + og * 8;
        #pragma unroll 4
        for (int j = 0; j < 128; j++) {
            float4 h4 = *(const float4*)(hrow + j * H0S);
            ulonglong2 wv0 = *(const ulonglong2*)(wrow + j * 64);
            ulonglong2 wv1 = *(const ulonglong2*)(wrow + j * 64 + 4);
            u64 hh;
            hh = pk2(h4.x, h4.x);
            fma2acc(acc[0],  hh, wv0.x); fma2acc(acc[1],  hh, wv0.y);
            fma2acc(acc[2],  hh, wv1.x); fma2acc(acc[3],  hh, wv1.y);
            hh = pk2(h4.y, h4.y);
            fma2acc(acc[4],  hh, wv0.x); fma2acc(acc[5],  hh, wv0.y);
            fma2acc(acc[6],  hh, wv1.x); fma2acc(acc[7],  hh, wv1.y);
            hh = pk2(h4.z, h4.z);
            fma2acc(acc[8],  hh, wv0.x); fma2acc(acc[9],  hh, wv0.y);
            fma2acc(acc[10], hh, wv1.x); fma2acc(acc[11], hh, wv1.y);
            hh = pk2(h4.w, h4.w);
            fma2acc(acc[12], hh, wv0.x); fma2acc(acc[13], hh, wv0.y);
            fma2acc(acc[14], hh, wv1.x); fma2acc(acc[15], hh, wv1.y);
        }
    }
    // epilogue: tanh -> fp16 -> g_h[s][64] (one uint4 = 8 halves; coalesced by og)
    #pragma unroll
    for (int s4 = 0; s4 < 4; s4++) {
        const int gs = base + 4 * sg + s4;
        if (gs < B) {
            float a, b, c, d;
            upk2(acc[s4 * 4 + 0], a, b);
            upk2(acc[s4 * 4 + 1], c, d);
            float2 t01 = tanh2(a, b);
            float2 t23 = tanh2(c, d);
            uint32_t p0 = f2h2(t01.x, t01.y);
            uint32_t p1 = f2h2(t23.x, t23.y);
            upk2(acc[s4 * 4 + 2], a, b);
            upk2(acc[s4 * 4 + 3], c, d);
            t01 = tanh2(a, b);
            t23 = tanh2(c, d);
            uint32_t p2 = f2h2(t01.x, t01.y);
            uint32_t p3 = f2h2(t23.x, t23.y);
            *(uint4*)(g_h + gs * 64 + og * 8) = make_uint4(p0, p1, p2, p3);
        }
    }
}

// ================= K2: scan + descriptors =================
__global__ void scan_kernel() {
    __shared__ int sStart[NE], sNb[NE], sDb[NE];
    const int t = threadIdx.x;
    if (t == 0) {
        int run = 0, nd = 0;
        for (int e = 0; e < NE; e++) {
            sStart[e] = run;
            int c = g_cnt[e];
            int nb = (c + ESPB - 1) / ESPB;
            sNb[e] = nb;
            sDb[e] = nd;
            nd += nb;
            run += c;
        }
        g_ndesc = nd;
    }
    __syncthreads();
    if (t < NE) {
        g_cursor[t] = sStart[t];
        const int nb = sNb[t], db = sDb[t], st = sStart[t], c = g_cnt[t];
        for (int b = 0; b < nb; b++) {
            g_desc_e[db + b] = t;
            g_desc_s[db + b] = st + b * ESPB;
            int rem = c - b * ESPB;
            g_desc_c[db + b] = rem < ESPB ? rem : ESPB;
        }
    }
}

// ================= K3: scatter into sorted perm =================
__global__ __launch_bounds__(256)
void scatter_kernel(int B) {
    __shared__ int sCnt[32], sRes[32];
    const int t = threadIdx.x;
    const int s = blockIdx.x * 256 + t;
    if (t < 32) sCnt[t] = 0;
    __syncthreads();
    int eid = 31;
    int myloc = 0;
    if (s < B) {
        eid = g_eid[s];
        myloc = atomicAdd(&sCnt[eid], 1);
    }
    __syncthreads();
    if (t < NE) {
        int c = sCnt[t];
        sRes[t] = c ? atomicAdd(&g_cursor[t], c) : 0;
    }
    __syncthreads();
    if (s < B && eid < NE) g_perm[sRes[eid] + myloc] = s;
}

// ================= K4: expert heads — 2 samples/thread, fp16 h =================
__global__ __launch_bounds__(256)
void expert_kernel(const float* __restrict__ Wa, const float* __restrict__ ba,
                   const float* __restrict__ Wb, const float* __restrict__ bb,
                   float* __restrict__ out)
{
    __shared__ float sWa[2048];
    __shared__ float sba[32], sWb0[32], sWb1[32], sbb[2];

    const int bid = blockIdx.x;
    if (bid >= g_ndesc) return;
    const int t = threadIdx.x;
    const int e   = g_desc_e[bid];
    const int st  = g_desc_s[bid];
    const int cnt = g_desc_c[bid];

    const bool v0 = (t < cnt);
    const bool v1 = (t + 256 < cnt);
    const int s0 = g_perm[st + (v0 ? t : 0)];
    const int s1 = g_perm[st + (v1 ? t + 256 : 0)];
    const uint2* ha = (const uint2*)(g_h + s0 * 64);   // 8 chunks x 4 halves... see below
    const uint2* hb = (const uint2*)(g_h + s1 * 64);
    // NOTE: we use uint4 chunks (8 halves) — 8 chunks cover all 64 h values.
    const uint4* ha4 = (const uint4*)ha;
    const uint4* hb4 = (const uint4*)hb;

    // depth-1 pipeline primed before staging (L2 latency hides behind staging+bar)
    uint4 hca = ha4[0], hna = ha4[1];
    uint4 hcb = hb4[0], hnb = hb4[1];

    ((float4*)sWa)[t]       = ((const float4*)(Wa + e * 2048))[t];
    ((float4*)sWa)[t + 256] = ((const float4*)(Wa + e * 2048))[t + 256];
    if (t < 32) {
        sba[t]  = ba[e * 32 + t];
        sWb0[t] = Wb[e * 64 + 2 * t];
        sWb1[t] = Wb[e * 64 + 2 * t + 1];
    }
    if (t < 2) sbb[t] = bb[e * 2 + t];
    __syncthreads();

    u64 ga[16], gb[16];
    #pragma unroll
    for (int q = 0; q < 16; q++) {
        u64 b2 = *(const u64*)(sba + 2 * q);
        ga[q] = b2; gb[q] = b2;
    }

    #pragma unroll
    for (int c = 0; c < 8; c++) {       // FIX: 8 chunks of 8 halves = all 64 h values
        uint4 Ua = hca, Ub = hcb;
        hca = hna; hcb = hnb;
        if (c < 6) { hna = ha4[c + 2]; hnb = hb4[c + 2]; }
        #pragma unroll
        for (int p = 0; p < 4; p++) {   // each uint32 = 2 h values (rows j0, j0+1)
            const uint32_t wa_ = (p == 0) ? Ua.x : (p == 1) ? Ua.y : (p == 2) ? Ua.z : Ua.w;
            const uint32_t wb_ = (p == 0) ? Ub.x : (p == 1) ? Ub.y : (p == 2) ? Ub.z : Ub.w;
            const float2 fa = h22f2(wa_);
            const float2 fb = h22f2(wb_);
            const int j0 = 8 * c + 2 * p;
            const u64 hha0 = pk2(fa.x, fa.x), hha1 = pk2(fa.y, fa.y);
            const u64 hhb0 = pk2(fb.x, fb.x), hhb1 = pk2(fb.y, fb.y);
            const ulonglong2* w0 = (const ulonglong2*)(sWa + j0 * 32);
            const ulonglong2* w1 = (const ulonglong2*)(sWa + (j0 + 1) * 32);
            #pragma unroll
            for (int r = 0; r < 8; r++) {
                ulonglong2 wv = w0[r];
                fma2acc(ga[2*r],   hha0, wv.x);
                fma2acc(gb[2*r],   hhb0, wv.x);
                fma2acc(ga[2*r+1], hha0, wv.y);
                fma2acc(gb[2*r+1], hhb0, wv.y);
            }
            #pragma unroll
            for (int r = 0; r < 8; r++) {
                ulonglong2 wv = w1[r];
                fma2acc(ga[2*r],   hha1, wv.x);
                fma2acc(gb[2*r],   hhb1, wv.x);
                fma2acc(ga[2*r+1], hha1, wv.y);
                fma2acc(gb[2*r+1], hhb1, wv.y);
            }
        }
    }

    u64 Pa0 = 0, Pa1 = 0, Pb0 = 0, Pb1 = 0;
    #pragma unroll
    for (int q = 0; q < 16; q++) {
        const u64 w0 = *(const u64*)(sWb0 + 2 * q);
        const u64 w1 = *(const u64*)(sWb1 + 2 * q);
        float a, b;
        upk2(ga[q], a, b);
        float2 tg = tanh2(a, b);
        u64 G = pk2(tg.x, tg.y);
        fma2acc(Pa0, G, w0);
        fma2acc(Pa1, G, w1);
        upk2(gb[q], a, b);
        tg = tanh2(a, b);
        G = pk2(tg.x, tg.y);
        fma2acc(Pb0, G, w0);
        fma2acc(Pb1, G, w1);
    }
    {
        float u, v;
        upk2(Pa0, u, v); float p0 = u + v + sbb[0];
        upk2(Pa1, u, v); float p1 = u + v + sbb[1];
        float r = rsqrtf(fmaf(p0, p0, fmaf(p1, p1, 1e-6f)));
        if (v0) ((float2*)out)[s0] = make_float2(p0 * r, p1 * r);
        upk2(Pb0, u, v); p0 = u + v + sbb[0];
        upk2(Pb1, u, v); p1 = u + v + sbb[1];
        r = rsqrtf(fmaf(p0, p0, fmaf(p1, p1, 1e-6f)));
        if (v1) ((float2*)out)[s1] = make_float2(p0 * r, p1 * r);
    }
}

// ================= K5: reset histogram for next call (runs last) =================
__global__ void init_kernel() {
    if (threadIdx.x < 32) g_cnt[threadIdx.x] = 0;
}

// ================= host =================
extern "C" void kernel_launch(void* const* d_in, const int* in_sizes, int n_in,
                              void* d_out, int out_size) {
    const float* x  = (const float*)d_in[0];
    const int*   nn = (const int*)  d_in[1];
    const int*   ll = (const int*)  d_in[2];
    const int*   mm = (const int*)  d_in[3];
    const float* W0 = (const float*)d_in[4];
    const float* b0 = (const float*)d_in[5];
    const float* W1 = (const float*)d_in[6];
    const float* b1 = (const float*)d_in[7];
    const float* Wa = (const float*)d_in[8];
    const float* ba = (const float*)d_in[9];
    const float* Wb = (const float*)d_in[10];
    const float* bb = (const float*)d_in[11];
    float* out = (float*)d_out;

    const int B = in_sizes[1];

    static int attr_set = 0;
    if (!attr_set) {
        cudaFuncSetAttribute(trunk_kernel,
                             cudaFuncAttributeMaxDynamicSharedMemorySize, T_SMEM_BYTES);
        attr_set = 1;
    }

    trunk_kernel<<<(B + TSPB - 1) / TSPB, 256, T_SMEM_BYTES>>>(
        x, nn, ll, mm, W0, b0, W1, b1, B);
    scan_kernel<<<1, 32>>>();
    scatter_kernel<<<(B + 255) / 256, 256>>>(B);
    expert_kernel<<<(B + ESPB - 1) / ESPB + NE, 256>>>(Wa, ba, Wb, bb, out);
    init_kernel<<<1, 32>>>();
}

// round 17
// speedup vs baseline: 1.5719x; 1.0193x over previous
#include <cuda_runtime.h>
#include <cuda_fp16.h>
#include <stdint.h>

#define MAXB 262144
#define TSPB 128            // trunk samples per block
#define ESPB 512            // expert samples per block (2 per thread)
#define NE 30
#define H0S 132             // h0T row stride (floats)
#define NDESC_MAX (MAXB / ESPB + NE + 2)

typedef unsigned long long u64;

// ---------------- device scratch (allocation-free) ----------------
__device__ __half g_h[MAXB * 64];    // h in fp16 (|h|<1): halves DRAM/L2 traffic
__device__ int   g_eid[MAXB];
__device__ int   g_perm[MAXB];
__device__ int   g_cnt[32];          // statically zero for the first call
__device__ int   g_cursor[32];
__device__ int   g_desc_e[NDESC_MAX];
__device__ int   g_desc_s[NDESC_MAX];
__device__ int   g_desc_c[NDESC_MAX];
__device__ int   g_ndesc;

// ---------------- packed f32x2 helpers ----------------
__device__ __forceinline__ u64 pk2(float lo, float hi) {
    u64 r; asm("mov.b64 %0,{%1,%2};" : "=l"(r) : "f"(lo), "f"(hi)); return r;
}
__device__ __forceinline__ void upk2(u64 v, float& lo, float& hi) {
    asm("mov.b64 {%0,%1},%2;" : "=f"(lo), "=f"(hi) : "l"(v));
}
__device__ __forceinline__ u64 fma2v(u64 a, u64 b, u64 c) {
    u64 d; asm("fma.rn.f32x2 %0,%1,%2,%3;" : "=l"(d) : "l"(a), "l"(b), "l"(c)); return d;
}
__device__ __forceinline__ void fma2acc(u64& d, u64 a, u64 b) {
    asm("fma.rn.f32x2 %0,%1,%2,%0;" : "+l"(d) : "l"(a), "l"(b));
}
__device__ __forceinline__ u64 mul2v(u64 a, u64 b) {
    u64 d; asm("mul.rn.f32x2 %0,%1,%2;" : "=l"(d) : "l"(a), "l"(b)); return d;
}
__device__ __forceinline__ uint32_t f2h2(float a, float b) {
    __half2 h = __floats2half2_rn(a, b);
    return *(uint32_t*)&h;
}
__device__ __forceinline__ float2 h22f2(uint32_t v) {
    return __half22float2(*(__half2*)&v);
}

// packed pair tanh, Pade[7/6], FMA-pipe only (no MUFU)
__device__ __forceinline__ float2 tanh2(float a, float b) {
    a = fminf(fmaxf(a, -5.0f), 5.0f);
    b = fminf(fmaxf(b, -5.0f), 5.0f);
    u64 cc = pk2(a, b);
    u64 uu = mul2v(cc, cc);
    u64 p = fma2v(uu, pk2(7.3996004e-6f, 7.3996004e-6f), pk2(2.7972028e-3f, 2.7972028e-3f));
    p = fma2v(uu, p, pk2(0.12820513f, 0.12820513f));
    p = fma2v(uu, p, pk2(1.0f, 1.0f));
    p = mul2v(p, cc);
    u64 q = fma2v(uu, pk2(2.0718881e-4f, 2.0718881e-4f), pk2(0.023310023f, 0.023310023f));
    q = fma2v(uu, q, pk2(0.46153846f, 0.46153846f));
    q = fma2v(uu, q, pk2(1.0f, 1.0f));
    float q0, q1; upk2(q, q0, q1);
    float r0 = __int_as_float(0x7EF311C3 - __float_as_int(q0));
    float r1 = __int_as_float(0x7EF311C3 - __float_as_int(q1));
    u64 rr = pk2(r0, r1);
    u64 nq = mul2v(q, pk2(-1.0f, -1.0f));
    u64 two = pk2(2.0f, 2.0f);
    rr = mul2v(rr, fma2v(nq, rr, two));
    rr = mul2v(rr, fma2v(nq, rr, two));
    u64 res = mul2v(p, rr);
    float o0, o1; upk2(res, o0, o1);
    return make_float2(o0, o1);
}

// ================= K1: trunk (256 thr, 2 CTAs/SM; pipelined pass B) =========
#define T_OFF_W0  0
#define T_OFF_B0  384
#define T_OFF_B1  512
#define T_OFF_W1  576
#define T_OFF_H0T 8768
#define T_OFF_INT (8768 + 128 * H0S)
#define T_SMEM_FLOATS (T_OFF_INT + 32)
#define T_SMEM_BYTES  (T_SMEM_FLOATS * 4)    // ~102.8 KB -> 2 CTAs/SM

extern __shared__ float smem[];

__global__ __launch_bounds__(256, 2)
void trunk_kernel(const float* __restrict__ x,
                  const int* __restrict__ nn,
                  const int* __restrict__ ll,
                  const int* __restrict__ mm,
                  const float* __restrict__ W0, const float* __restrict__ b0,
                  const float* __restrict__ W1, const float* __restrict__ b1,
                  int B)
{
    float* sW0  = smem + T_OFF_W0;
    float* sb0  = smem + T_OFF_B0;
    float* sb1  = smem + T_OFF_B1;
    float* sW1  = smem + T_OFF_W1;
    float* sH0T = smem + T_OFF_H0T;
    int*   sCnt = (int*)(smem + T_OFF_INT);

    const int t = threadIdx.x;
    const int base = blockIdx.x * TSPB;

    for (int i = t; i < 384; i += 256) sW0[i] = W0[i];
    if (t < 128) sb0[t] = b0[t];
    #pragma unroll
    for (int i = 0; i < 8; i++) ((float4*)sW1)[t + 256 * i] = ((const float4*)W1)[t + 256 * i];
    if (t < 64) sb1[t] = b1[t];
    if (t < 31) sCnt[t] = 0;
    __syncthreads();

    // ---- pass A: h0 = tanh(x@W0+b0) -> h0T[j][s], 2 threads/sample ----
    const int sa = t & 127;
    const int ubase = (t >> 7) * 64;
    const int s = base + sa;
    const bool active = (s < B);
    float x0 = 0.f, x1 = 0.f, x2 = 0.f;
    if (active) {
        x0 = x[3 * s + 0];
        x1 = x[3 * s + 1];
        x2 = x[3 * s + 2];
    }
    if (t < 128) {
        int eid = NE;
        if (active) {
            int n = nn[s], l = ll[s], m = mm[s];
            eid = ((n - 1) * n * (2 * n - 1)) / 6 + l * l + l + m;
            g_eid[s] = eid;
        }
        if (eid < NE) atomicAdd(&sCnt[eid], 1);
    }
    {
        const u64 xx0 = pk2(x0, x0);
        const u64 xx1 = pk2(x1, x1);
        const u64 xx2 = pk2(x2, x2);
        float* hdst = sH0T + ubase * H0S + sa;
        #pragma unroll 8
        for (int up = 0; up < 32; up++) {
            const int u = ubase + 2 * up;
            float2 wa2 = *(const float2*)(sW0 + u);
            float2 wb2 = *(const float2*)(sW0 + 128 + u);
            float2 wc2 = *(const float2*)(sW0 + 256 + u);
            float2 bp2 = *(const float2*)(sb0 + u);
            u64 pre = fma2v(xx0, pk2(wa2.x, wa2.y),
                      fma2v(xx1, pk2(wb2.x, wb2.y),
                      fma2v(xx2, pk2(wc2.x, wc2.y), pk2(bp2.x, bp2.y))));
            float p0, p1; upk2(pre, p0, p1);
            float2 h = tanh2(p0, p1);
            hdst[0]   = h.x;
            hdst[H0S] = h.y;
            hdst += 2 * H0S;
        }
    }
    __syncthreads();

    if (t < 30) {
        int c = sCnt[t];
        if (c) atomicAdd(&g_cnt[t], c);
    }

    // ---- pass B: C[128x64] = h0T @ W1 ; og=t&7 (8 outs), sg=t>>3 (4 samples)
    //      explicit depth-1 software pipeline on the LDS loads ----
    const int og = t & 7;
    const int sg = t >> 3;
    u64 acc[16];
    {
        const ulonglong2* bi = (const ulonglong2*)(sb1 + og * 8);
        ulonglong2 b01 = bi[0], b23 = bi[1];
        #pragma unroll
        for (int s4 = 0; s4 < 4; s4++) {
            acc[s4 * 4 + 0] = b01.x; acc[s4 * 4 + 1] = b01.y;
            acc[s4 * 4 + 2] = b23.x; acc[s4 * 4 + 3] = b23.y;
        }
    }
    {
        const float* hrow = sH0T + 4 * sg;
        const float* wrow = sW1 + og * 8;
        float4 h4 = *(const float4*)(hrow);
        ulonglong2 wv0 = *(const ulonglong2*)(wrow);
        ulonglong2 wv1 = *(const ulonglong2*)(wrow + 4);
        #pragma unroll 2
        for (int j = 0; j < 128; j++) {
            const float4 h4c = h4;
            const ulonglong2 w0c = wv0, w1c = wv1;
            if (j < 127) {
                h4  = *(const float4*)(hrow + (j + 1) * H0S);
                wv0 = *(const ulonglong2*)(wrow + (j + 1) * 64);
                wv1 = *(const ulonglong2*)(wrow + (j + 1) * 64 + 4);
            }
            u64 hh;
            hh = pk2(h4c.x, h4c.x);
            fma2acc(acc[0],  hh, w0c.x); fma2acc(acc[1],  hh, w0c.y);
            fma2acc(acc[2],  hh, w1c.x); fma2acc(acc[3],  hh, w1c.y);
            hh = pk2(h4c.y, h4c.y);
            fma2acc(acc[4],  hh, w0c.x); fma2acc(acc[5],  hh, w0c.y);
            fma2acc(acc[6],  hh, w1c.x); fma2acc(acc[7],  hh, w1c.y);
            hh = pk2(h4c.z, h4c.z);
            fma2acc(acc[8],  hh, w0c.x); fma2acc(acc[9],  hh, w0c.y);
            fma2acc(acc[10], hh, w1c.x); fma2acc(acc[11], hh, w1c.y);
            hh = pk2(h4c.w, h4c.w);
            fma2acc(acc[12], hh, w0c.x); fma2acc(acc[13], hh, w0c.y);
            fma2acc(acc[14], hh, w1c.x); fma2acc(acc[15], hh, w1c.y);
        }
    }
    // epilogue: tanh -> fp16 -> g_h[s][64] (one uint4 = 8 halves; coalesced by og)
    #pragma unroll
    for (int s4 = 0; s4 < 4; s4++) {
        const int gs = base + 4 * sg + s4;
        if (gs < B) {
            float a, b, c, d;
            upk2(acc[s4 * 4 + 0], a, b);
            upk2(acc[s4 * 4 + 1], c, d);
            float2 t01 = tanh2(a, b);
            float2 t23 = tanh2(c, d);
            uint32_t p0 = f2h2(t01.x, t01.y);
            uint32_t p1 = f2h2(t23.x, t23.y);
            upk2(acc[s4 * 4 + 2], a, b);
            upk2(acc[s4 * 4 + 3], c, d);
            t01 = tanh2(a, b);
            t23 = tanh2(c, d);
            uint32_t p2 = f2h2(t01.x, t01.y);
            uint32_t p3 = f2h2(t23.x, t23.y);
            *(uint4*)(g_h + gs * 64 + og * 8) = make_uint4(p0, p1, p2, p3);
        }
    }
}

// ================= K2: scan + descriptors (+ histogram reset for next call) ======
__global__ void scan_kernel() {
    __shared__ int sStart[NE], sNb[NE], sDb[NE];
    const int t = threadIdx.x;
    if (t == 0) {
        int run = 0, nd = 0;
        for (int e = 0; e < NE; e++) {
            sStart[e] = run;
            int c = g_cnt[e];
            int nb = (c + ESPB - 1) / ESPB;
            sNb[e] = nb;
            sDb[e] = nd;
            nd += nb;
            run += c;
        }
        g_ndesc = nd;
    }
    __syncthreads();
    if (t < NE) {
        g_cursor[t] = sStart[t];
        const int nb = sNb[t], db = sDb[t], st = sStart[t], c = g_cnt[t];
        for (int b = 0; b < nb; b++) {
            g_desc_e[db + b] = t;
            g_desc_s[db + b] = st + b * ESPB;
            int rem = c - b * ESPB;
            g_desc_c[db + b] = rem < ESPB ? rem : ESPB;
        }
    }
    __syncthreads();
    if (t < 32) g_cnt[t] = 0;    // reset for next graph replay (all reads done)
}

// ================= K3: scatter into sorted perm =================
__global__ __launch_bounds__(256)
void scatter_kernel(int B) {
    __shared__ int sCnt[32], sRes[32];
    const int t = threadIdx.x;
    const int s = blockIdx.x * 256 + t;
    if (t < 32) sCnt[t] = 0;
    __syncthreads();
    int eid = 31;
    int myloc = 0;
    if (s < B) {
        eid = g_eid[s];
        myloc = atomicAdd(&sCnt[eid], 1);
    }
    __syncthreads();
    if (t < NE) {
        int c = sCnt[t];
        sRes[t] = c ? atomicAdd(&g_cursor[t], c) : 0;
    }
    __syncthreads();
    if (s < B && eid < NE) g_perm[sRes[eid] + myloc] = s;
}

// ================= K4: expert heads — 2 samples/thread, fp16 h (R16) ===========
__global__ __launch_bounds__(256)
void expert_kernel(const float* __restrict__ Wa, const float* __restrict__ ba,
                   const float* __restrict__ Wb, const float* __restrict__ bb,
                   float* __restrict__ out)
{
    __shared__ float sWa[2048];
    __shared__ float sba[32], sWb0[32], sWb1[32], sbb[2];

    const int bid = blockIdx.x;
    if (bid >= g_ndesc) return;
    const int t = threadIdx.x;
    const int e   = g_desc_e[bid];
    const int st  = g_desc_s[bid];
    const int cnt = g_desc_c[bid];

    const bool v0 = (t < cnt);
    const bool v1 = (t + 256 < cnt);
    const int s0 = g_perm[st + (v0 ? t : 0)];
    const int s1 = g_perm[st + (v1 ? t + 256 : 0)];
    const uint4* ha4 = (const uint4*)(g_h + s0 * 64);   // 8 chunks x 8 halves
    const uint4* hb4 = (const uint4*)(g_h + s1 * 64);

    // depth-1 pipeline primed before staging (L2 latency hides behind staging+bar)
    uint4 hca = ha4[0], hna = ha4[1];
    uint4 hcb = hb4[0], hnb = hb4[1];

    ((float4*)sWa)[t]       = ((const float4*)(Wa + e * 2048))[t];
    ((float4*)sWa)[t + 256] = ((const float4*)(Wa + e * 2048))[t + 256];
    if (t < 32) {
        sba[t]  = ba[e * 32 + t];
        sWb0[t] = Wb[e * 64 + 2 * t];
        sWb1[t] = Wb[e * 64 + 2 * t + 1];
    }
    if (t < 2) sbb[t] = bb[e * 2 + t];
    __syncthreads();

    u64 ga[16], gb[16];
    #pragma unroll
    for (int q = 0; q < 16; q++) {
        u64 b2 = *(const u64*)(sba + 2 * q);
        ga[q] = b2; gb[q] = b2;
    }

    #pragma unroll
    for (int c = 0; c < 8; c++) {       // 8 chunks of 8 halves = all 64 h values
        uint4 Ua = hca, Ub = hcb;
        hca = hna; hcb = hnb;
        if (c < 6) { hna = ha4[c + 2]; hnb = hb4[c + 2]; }
        #pragma unroll
        for (int p = 0; p < 4; p++) {   // each uint32 = 2 h values (rows j0, j0+1)
            const uint32_t wa_ = (p == 0) ? Ua.x : (p == 1) ? Ua.y : (p == 2) ? Ua.z : Ua.w;
            const uint32_t wb_ = (p == 0) ? Ub.x : (p == 1) ? Ub.y : (p == 2) ? Ub.z : Ub.w;
            const float2 fa = h22f2(wa_);
            const float2 fb = h22f2(wb_);
            const int j0 = 8 * c + 2 * p;
            const u64 hha0 = pk2(fa.x, fa.x), hha1 = pk2(fa.y, fa.y);
            const u64 hhb0 = pk2(fb.x, fb.x), hhb1 = pk2(fb.y, fb.y);
            const ulonglong2* w0 = (const ulonglong2*)(sWa + j0 * 32);
            const ulonglong2* w1 = (const ulonglong2*)(sWa + (j0 + 1) * 32);
            #pragma unroll
            for (int r = 0; r < 8; r++) {
                ulonglong2 wv = w0[r];
                fma2acc(ga[2*r],   hha0, wv.x);
                fma2acc(gb[2*r],   hhb0, wv.x);
                fma2acc(ga[2*r+1], hha0, wv.y);
                fma2acc(gb[2*r+1], hhb0, wv.y);
            }
            #pragma unroll
            for (int r = 0; r < 8; r++) {
                ulonglong2 wv = w1[r];
                fma2acc(ga[2*r],   hha1, wv.x);
                fma2acc(gb[2*r],   hhb1, wv.x);
                fma2acc(ga[2*r+1], hha1, wv.y);
                fma2acc(gb[2*r+1], hhb1, wv.y);
            }
        }
    }

    u64 Pa0 = 0, Pa1 = 0, Pb0 = 0, Pb1 = 0;
    #pragma unroll
    for (int q = 0; q < 16; q++) {
        const u64 w0 = *(const u64*)(sWb0 + 2 * q);
        const u64 w1 = *(const u64*)(sWb1 + 2 * q);
        float a, b;
        upk2(ga[q], a, b);
        float2 tg = tanh2(a, b);
        u64 G = pk2(tg.x, tg.y);
        fma2acc(Pa0, G, w0);
        fma2acc(Pa1, G, w1);
        upk2(gb[q], a, b);
        tg = tanh2(a, b);
        G = pk2(tg.x, tg.y);
        fma2acc(Pb0, G, w0);
        fma2acc(Pb1, G, w1);
    }
    {
        float u, v;
        upk2(Pa0, u, v); float p0 = u + v + sbb[0];
        upk2(Pa1, u, v); float p1 = u + v + sbb[1];
        float r = rsqrtf(fmaf(p0, p0, fmaf(p1, p1, 1e-6f)));
        if (v0) ((float2*)out)[s0] = make_float2(p0 * r, p1 * r);
        upk2(Pb0, u, v); p0 = u + v + sbb[0];
        upk2(Pb1, u, v); p1 = u + v + sbb[1];
        r = rsqrtf(fmaf(p0, p0, fmaf(p1, p1, 1e-6f)));
        if (v1) ((float2*)out)[s1] = make_float2(p0 * r, p1 * r);
    }
}

// ================= host =================
extern "C" void kernel_launch(void* const* d_in, const int* in_sizes, int n_in,
                              void* d_out, int out_size) {
    const float* x  = (const float*)d_in[0];
    const int*   nn = (const int*)  d_in[1];
    const int*   ll = (const int*)  d_in[2];
    const int*   mm = (const int*)  d_in[3];
    const float* W0 = (const float*)d_in[4];
    const float* b0 = (const float*)d_in[5];
    const float* W1 = (const float*)d_in[6];
    const float* b1 = (const float*)d_in[7];
    const float* Wa = (const float*)d_in[8];
    const float* ba = (const float*)d_in[9];
    const float* Wb = (const float*)d_in[10];
    const float* bb = (const float*)d_in[11];
    float* out = (float*)d_out;

    const int B = in_sizes[1];

    static int attr_set = 0;
    if (!attr_set) {
        cudaFuncSetAttribute(trunk_kernel,
                             cudaFuncAttributeMaxDynamicSharedMemorySize, T_SMEM_BYTES);
        attr_set = 1;
    }

    trunk_kernel<<<(B + TSPB - 1) / TSPB, 256, T_SMEM_BYTES>>>(
        x, nn, ll, mm, W0, b0, W1, b1, B);
    scan_kernel<<<1, 32>>>();
    scatter_kernel<<<(B + 255) / 256, 256>>>(B);
    expert_kernel<<<(B + ESPB - 1) / ESPB + NE, 256>>>(Wa, ba, Wb, bb, out);
}